// round 14
// baseline (speedup 1.0000x reference)
#include <cuda_runtime.h>
#include <cuda_fp16.h>
#include <math.h>
#include <stdint.h>

#define D 256
#define N_TGT 40000
#define NNZ_MAX 300000
#define N_TGT_PAD 40960
#define BM 64
#define NTILE (N_TGT / BM)       // 625
#define GRID 148                  // persistent: 1 CTA per SM
#define THREADS 512               // 8 consumer warps + 8 producer warps

// ---------------- device scratch ----------------
__device__ __half g_wt_h[D * D];                   // W^T [n][k], fp16
__device__ int   g_row_cnt[N_TGT_PAD];
__device__ int   g_loc[N_TGT_PAD];
__device__ int   g_blk[40];
__device__ int   g_blk_off[40];
__device__ int2  g_csr_pack[NNZ_MAX];

// ---------------- smem layout (bytes) ----------------
// rows padded to 264 fp16 (528 B): conflict-free frag LDS + 16B STS
#define A_STRIDE 264
#define A_TILE_B (64 * 528)           // 33792
#define OFF_A0 0
#define OFF_A1 33792
#define OFF_B  67584                   // 256 x 528 = 135168
#define OFF_BIAS  202752
#define OFF_GAMMA 203776
#define OFF_BETA  204800
#define OFF_PART  205824               // 64 x 4 float2
#define OFF_STAT  207872               // 64 float2
#define SMEM_TOTAL 208384

__device__ __forceinline__ uint32_t smem_u32(const void* p) {
    uint32_t a;
    asm("{ .reg .u64 t; cvta.to.shared.u64 t, %1; cvt.u32.u64 %0, t; }"
        : "=r"(a) : "l"(p));
    return a;
}

__device__ __forceinline__ void cpasync16(uint32_t dst, const void* src) {
    asm volatile("cp.async.ca.shared.global [%0], [%1], 16;"
                 :: "r"(dst), "l"(src) : "memory");
}

__device__ __forceinline__ void mma_fp16(float* c, const uint32_t* a,
                                         uint32_t b0, uint32_t b1) {
    asm volatile(
        "mma.sync.aligned.m16n8k16.row.col.f32.f16.f16.f32 "
        "{%0,%1,%2,%3}, {%4,%5,%6,%7}, {%8,%9}, {%0,%1,%2,%3};"
        : "+f"(c[0]), "+f"(c[1]), "+f"(c[2]), "+f"(c[3])
        : "r"(a[0]), "r"(a[1]), "r"(a[2]), "r"(a[3]), "r"(b0), "r"(b1));
}

// ---------------------------------------------------------------------------
// CSR build (proven)
// ---------------------------------------------------------------------------
__global__ void hist_kernel(const int* __restrict__ rows, int nnz) {
    int e = blockIdx.x * 256 + threadIdx.x;
    if (e < nnz) atomicAdd(&g_row_cnt[__ldg(rows + e)], 1);
}

__global__ __launch_bounds__(256) void scanA_kernel() {
    __shared__ int swarp[8];
    const int b = blockIdx.x, tid = threadIdx.x;
    const int lane = tid & 31, wid = tid >> 5;
    int4 v = ((const int4*)g_row_cnt)[b * 256 + tid];
    int tsum = v.x + v.y + v.z + v.w;
    int inc = tsum;
#pragma unroll
    for (int o = 1; o < 32; o <<= 1) {
        int n = __shfl_up_sync(0xffffffffu, inc, o);
        if (lane >= o) inc += n;
    }
    if (lane == 31) swarp[wid] = inc;
    __syncthreads();
    if (wid == 0 && lane < 8) {
        int s = swarp[lane];
        int si = s;
#pragma unroll
        for (int o = 1; o < 8; o <<= 1) {
            int n = __shfl_up_sync(0xffu, si, o);
            if (lane >= o) si += n;
        }
        swarp[lane] = si - s;
        if (lane == 7) g_blk[b] = si;
    }
    __syncthreads();
    int base = swarp[wid] + inc - tsum;
    int4 o4;
    o4.x = base;
    o4.y = base + v.x;
    o4.z = o4.y + v.y;
    o4.w = o4.z + v.z;
    ((int4*)g_loc)[b * 256 + tid] = o4;
}

__global__ void scanB_kernel() {
    int l = threadIdx.x;
    int s0 = (2 * l < 40) ? g_blk[2 * l] : 0;
    int s1 = (2 * l + 1 < 40) ? g_blk[2 * l + 1] : 0;
    int p = s0 + s1, inc = p;
#pragma unroll
    for (int o = 1; o < 32; o <<= 1) {
        int n = __shfl_up_sync(0xffffffffu, inc, o);
        if (l >= o) inc += n;
    }
    int excl = inc - p;
    if (2 * l < 40) g_blk_off[2 * l] = excl;
    if (2 * l + 1 < 40) g_blk_off[2 * l + 1] = excl + s0;
}

__global__ void bucket_kernel(const int* __restrict__ rows,
                              const int* __restrict__ cols,
                              const float* __restrict__ vals, int nnz) {
    int e = blockIdx.x * 256 + threadIdx.x;
    if (e >= nnz) return;
    int r = __ldg(rows + e);
    int lp = atomicAdd(&g_loc[r], 1);
    int pos = lp + g_blk_off[r >> 10];
    g_csr_pack[pos] = make_int2(__ldg(cols + e),
                                __float_as_int(__ldg(vals + e)));
}

// ---------------------------------------------------------------------------
// W transpose -> fp16: 32x32 tiles.
// ---------------------------------------------------------------------------
__global__ __launch_bounds__(256) void wconv_kernel(const float* __restrict__ W) {
    __shared__ float t[32][33];
    const int tid = threadIdx.x;
    const int k0 = (blockIdx.x >> 3) * 32;
    const int n0 = (blockIdx.x & 7) * 32;
    {
        int row = tid >> 3, c4 = tid & 7;
        float4 v = __ldg((const float4*)(W + (size_t)(k0 + row) * D + n0 + c4 * 4));
        t[row][c4 * 4 + 0] = v.x;
        t[row][c4 * 4 + 1] = v.y;
        t[row][c4 * 4 + 2] = v.z;
        t[row][c4 * 4 + 3] = v.w;
    }
    __syncthreads();
    {
        int nl = tid >> 3, kq = (tid & 7) * 4;
        __half2 p0 = __floats2half2_rn(t[kq][nl], t[kq + 1][nl]);
        __half2 p1 = __floats2half2_rn(t[kq + 2][nl], t[kq + 3][nl]);
        uint2 pk = make_uint2(*(uint32_t*)&p0, *(uint32_t*)&p1);
        *(uint2*)(g_wt_h + (size_t)(n0 + nl) * D + k0 + kq) = pk;
    }
}

// ---------------------------------------------------------------------------
// Fused persistent kernel: producer warps gather CSR rows of x into smem A
// tiles (fp16), consumer warps do MMA + bias + LN + GELU.  Double-buffered,
// one __syncthreads per tile.
// ---------------------------------------------------------------------------
extern __shared__ char dynsmem[];

__device__ __forceinline__ void gather_tile(char* sm, uint32_t bufoff, int t,
                                            int ptid, const float* __restrict__ x) {
    const int pwid = ptid >> 5;
    const int lane = ptid & 31;
#pragma unroll 1
    for (int rr = 0; rr < 8; ++rr) {
        const int row = rr * 8 + pwid;
        const int r = t * BM + row;
        const int cnt = g_row_cnt[r];
        const int start = g_loc[r] + g_blk_off[r >> 10] - cnt;
        const int2* ep = g_csr_pack + start;

        float a[8];
#pragma unroll
        for (int q = 0; q < 8; ++q) a[q] = 0.f;

        int j = 0;
        for (; j + 2 <= cnt; j += 2) {
            int2 e0 = __ldg(ep + j);
            int2 e1 = __ldg(ep + j + 1);
            float v0 = __int_as_float(e0.y);
            float v1 = __int_as_float(e1.y);
            const float4* xs0 = (const float4*)(x + (size_t)e0.x * D) + 2 * lane;
            const float4* xs1 = (const float4*)(x + (size_t)e1.x * D) + 2 * lane;
            float4 p0 = __ldg(xs0), p1 = __ldg(xs0 + 1);
            float4 q0 = __ldg(xs1), q1 = __ldg(xs1 + 1);
            a[0] += v0 * p0.x; a[1] += v0 * p0.y; a[2] += v0 * p0.z; a[3] += v0 * p0.w;
            a[4] += v0 * p1.x; a[5] += v0 * p1.y; a[6] += v0 * p1.z; a[7] += v0 * p1.w;
            a[0] += v1 * q0.x; a[1] += v1 * q0.y; a[2] += v1 * q0.z; a[3] += v1 * q0.w;
            a[4] += v1 * q1.x; a[5] += v1 * q1.y; a[6] += v1 * q1.z; a[7] += v1 * q1.w;
        }
        if (j < cnt) {
            int2 e0 = __ldg(ep + j);
            float v0 = __int_as_float(e0.y);
            const float4* xs0 = (const float4*)(x + (size_t)e0.x * D) + 2 * lane;
            float4 p0 = __ldg(xs0), p1 = __ldg(xs0 + 1);
            a[0] += v0 * p0.x; a[1] += v0 * p0.y; a[2] += v0 * p0.z; a[3] += v0 * p0.w;
            a[4] += v0 * p1.x; a[5] += v0 * p1.y; a[6] += v0 * p1.z; a[7] += v0 * p1.w;
        }

        __half2 h0 = __floats2half2_rn(a[0], a[1]);
        __half2 h1 = __floats2half2_rn(a[2], a[3]);
        __half2 h2 = __floats2half2_rn(a[4], a[5]);
        __half2 h3 = __floats2half2_rn(a[6], a[7]);
        uint4 pack = make_uint4(*(uint32_t*)&h0, *(uint32_t*)&h1,
                                *(uint32_t*)&h2, *(uint32_t*)&h3);
        *(uint4*)(sm + bufoff + row * 528 + lane * 16) = pack;
    }
}

__global__ __launch_bounds__(THREADS, 1) void fused_gemm_kernel(
        const float* __restrict__ x,
        const float* __restrict__ bias,
        const float* __restrict__ gamma,
        const float* __restrict__ beta,
        float* __restrict__ out) {
    char* sm = dynsmem;
    const uint32_t sb = smem_u32(sm);
    const int tid = threadIdx.x;
    const bool consumer = tid < 256;

    // ---- prologue ----
    if (consumer) {
        ((float*)(sm + OFF_BIAS))[tid]  = bias[tid];
        ((float*)(sm + OFF_GAMMA))[tid] = gamma[tid];
        ((float*)(sm + OFF_BETA))[tid]  = beta[tid];
        // resident B = Wt fp16 [256][256]
#pragma unroll
        for (int i = 0; i < 32; ++i) {
            int task = i * 256 + tid;
            int n = task >> 5, seg = task & 31;
            cpasync16(sb + OFF_B + n * 528 + seg * 16, g_wt_h + n * 256 + seg * 8);
        }
        asm volatile("cp.async.commit_group;" ::: "memory");
        asm volatile("cp.async.wait_group 0;" ::: "memory");
    } else {
        gather_tile(sm, OFF_A0, blockIdx.x, tid - 256, x);
    }

    const int wid = tid >> 5;
    const int lane = tid & 31;
    const int gr = lane >> 2;
    const int tc = lane & 3;
    const int warp_m = wid & 1;
    const int warp_n = wid >> 1;

    const float* sBias = (const float*)(sm + OFF_BIAS);
    const float* sG    = (const float*)(sm + OFF_GAMMA);
    const float* sBe   = (const float*)(sm + OFF_BETA);
    float2* sPart = (float2*)(sm + OFF_PART);
    float2* sStat = (float2*)(sm + OFF_STAT);

    int i = 0;
#pragma unroll 1
    for (int t = blockIdx.x; t < NTILE; t += GRID, ++i) {
        __syncthreads();   // buf[i&1] filled; buf[(i+1)&1] free

        if (consumer) {
            const uint16_t* pA = (const uint16_t*)(sm + ((i & 1) ? OFF_A1 : OFF_A0));
            const uint16_t* pB = (const uint16_t*)(sm + OFF_B);

            float acc[2][8][4];
#pragma unroll
            for (int mt = 0; mt < 2; ++mt)
#pragma unroll
                for (int nt = 0; nt < 8; ++nt)
#pragma unroll
                    for (int q = 0; q < 4; ++q) acc[mt][nt][q] = 0.f;

#pragma unroll
            for (int ks = 0; ks < 16; ++ks) {
                uint32_t a[2][4];
#pragma unroll
                for (int mt = 0; mt < 2; ++mt) {
                    const uint16_t* ph = pA + (warp_m * 32 + mt * 16 + gr) * A_STRIDE
                                            + ks * 16 + tc * 2;
                    a[mt][0] = *(const uint32_t*)(ph);
                    a[mt][1] = *(const uint32_t*)(ph + 8 * A_STRIDE);
                    a[mt][2] = *(const uint32_t*)(ph + 8);
                    a[mt][3] = *(const uint32_t*)(ph + 8 * A_STRIDE + 8);
                }
#pragma unroll
                for (int nt = 0; nt < 8; ++nt) {
                    const uint16_t* pb = pB + (warp_n * 64 + nt * 8 + gr) * A_STRIDE
                                            + ks * 16 + tc * 2;
                    uint32_t b0 = *(const uint32_t*)(pb);
                    uint32_t b1 = *(const uint32_t*)(pb + 8);
                    mma_fp16(acc[0][nt], a[0], b0, b1);
                    mma_fp16(acc[1][nt], a[1], b0, b1);
                }
            }

            // ---- epilogue: bias, LN stats (consumer-only barriers), GELU ----
            float s[2][2], q[2][2];
#pragma unroll
            for (int mt = 0; mt < 2; ++mt)
#pragma unroll
                for (int h = 0; h < 2; ++h) { s[mt][h] = 0.f; q[mt][h] = 0.f; }

#pragma unroll
            for (int mt = 0; mt < 2; ++mt)
#pragma unroll
                for (int nt = 0; nt < 8; ++nt) {
                    int c = warp_n * 64 + nt * 8 + tc * 2;
                    float b0 = sBias[c], b1 = sBias[c + 1];
#pragma unroll
                    for (int h = 0; h < 2; ++h) {
                        float v0 = acc[mt][nt][2 * h] + b0;
                        float v1 = acc[mt][nt][2 * h + 1] + b1;
                        acc[mt][nt][2 * h] = v0;
                        acc[mt][nt][2 * h + 1] = v1;
                        s[mt][h] += v0 + v1;
                        q[mt][h] += v0 * v0 + v1 * v1;
                    }
                }
#pragma unroll
            for (int mt = 0; mt < 2; ++mt)
#pragma unroll
                for (int h = 0; h < 2; ++h) {
#pragma unroll
                    for (int o = 1; o < 4; o <<= 1) {
                        s[mt][h] += __shfl_xor_sync(0xffffffffu, s[mt][h], o);
                        q[mt][h] += __shfl_xor_sync(0xffffffffu, q[mt][h], o);
                    }
                }
            if (tc == 0) {
#pragma unroll
                for (int mt = 0; mt < 2; ++mt)
#pragma unroll
                    for (int h = 0; h < 2; ++h) {
                        int r = warp_m * 32 + mt * 16 + 8 * h + gr;
                        sPart[r * 4 + warp_n] = make_float2(s[mt][h], q[mt][h]);
                    }
            }
            asm volatile("bar.sync 1, 256;" ::: "memory");
            if (tid < 64) {
                float2 p0 = sPart[tid * 4 + 0];
                float2 p1 = sPart[tid * 4 + 1];
                float2 p2 = sPart[tid * 4 + 2];
                float2 p3 = sPart[tid * 4 + 3];
                float S = p0.x + p1.x + p2.x + p3.x;
                float Q = p0.y + p1.y + p2.y + p3.y;
                float mu = S * (1.f / 256.f);
                float var = Q * (1.f / 256.f) - mu * mu;
                sStat[tid] = make_float2(mu, rsqrtf(fmaxf(var, 0.f) + 1e-5f));
            }
            asm volatile("bar.sync 1, 256;" ::: "memory");

#pragma unroll
            for (int mt = 0; mt < 2; ++mt)
#pragma unroll
                for (int h = 0; h < 2; ++h) {
                    int r = warp_m * 32 + mt * 16 + 8 * h + gr;
                    float2 st = sStat[r];
                    float* orow = out + (size_t)(t * BM + r) * D;
#pragma unroll
                    for (int nt = 0; nt < 8; ++nt) {
                        int c = warp_n * 64 + nt * 8 + tc * 2;
                        float t0 = (acc[mt][nt][2 * h] - st.x) * st.y * sG[c] + sBe[c];
                        float t1 = (acc[mt][nt][2 * h + 1] - st.x) * st.y * sG[c + 1] + sBe[c + 1];
                        float2 g;
                        g.x = 0.5f * t0 * (1.f + erff(t0 * 0.70710678118654752f));
                        g.y = 0.5f * t1 * (1.f + erff(t1 * 0.70710678118654752f));
                        *(float2*)(orow + c) = g;
                    }
                }
        } else {
            // producers: gather next tile into the other buffer
            if (t + GRID < NTILE)
                gather_tile(sm, (i + 1) & 1 ? OFF_A1 : OFF_A0, t + GRID,
                            tid - 256, x);
        }
    }
}

// ---------------------------------------------------------------------------
// Launch
// ---------------------------------------------------------------------------
extern "C" void kernel_launch(void* const* d_in, const int* in_sizes, int n_in,
                              void* d_out, int out_size) {
    const float* x     = (const float*)d_in[0];
    const int*   rows  = (const int*)d_in[1];
    const int*   cols  = (const int*)d_in[2];
    const float* vals  = (const float*)d_in[3];
    const float* W     = (const float*)d_in[4];
    const float* bias  = (const float*)d_in[5];
    const float* gamma = (const float*)d_in[6];
    const float* beta  = (const float*)d_in[7];

    const int nnz = in_sizes[1];
    const int eblk = (nnz + 255) / 256;

    void* cnt_ptr = nullptr;
    cudaGetSymbolAddress(&cnt_ptr, g_row_cnt);
    cudaMemsetAsync(cnt_ptr, 0, N_TGT_PAD * sizeof(int));

    hist_kernel<<<eblk, 256>>>(rows, nnz);
    scanA_kernel<<<40, 256>>>();
    scanB_kernel<<<1, 32>>>();
    bucket_kernel<<<eblk, 256>>>(rows, cols, vals, nnz);
    wconv_kernel<<<64, 256>>>(W);

    cudaFuncSetAttribute(fused_gemm_kernel,
                         cudaFuncAttributeMaxDynamicSharedMemorySize,
                         SMEM_TOTAL);
    fused_gemm_kernel<<<GRID, THREADS, SMEM_TOTAL>>>(
        x, bias, gamma, beta, (float*)d_out);
}

// round 15
// speedup vs baseline: 1.3573x; 1.3573x over previous
#include <cuda_runtime.h>
#include <cuda_fp16.h>
#include <math.h>
#include <stdint.h>

#define D 256
#define N_TGT 40000
#define NNZ_MAX 300000
#define N_TGT_PAD 40960
#define BM 64
#define NTILE (N_TGT / BM)       // 625
#define GRID 148                  // persistent: 1 CTA per SM

// ---------------- device scratch ----------------
__device__ __half g_mapped_h[(size_t)N_TGT * D];   // SpMM result, fp16
__device__ __half g_wt_h[D * D];                   // W^T [n][k], fp16
__device__ int   g_row_cnt[N_TGT_PAD];
__device__ int   g_loc[N_TGT_PAD];
__device__ int   g_blk[40];
__device__ int   g_blk_off[40];
__device__ int   g_ticket;        // zero-init; self-resetting each call
__device__ int2  g_csr_pack[NNZ_MAX];

// ---------------- GEMM smem layout (bytes) ----------------
#define A_STRIDE 264
#define A_TILE_B (64 * 528)
#define OFF_A0 0
#define OFF_A1 33792
#define OFF_B  67584
#define OFF_BIAS  202752
#define OFF_GAMMA 203776
#define OFF_BETA  204800
#define OFF_PART  205824
#define OFF_STAT  207872
#define SMEM_TOTAL 208384

__device__ __forceinline__ uint32_t smem_u32(const void* p) {
    uint32_t a;
    asm("{ .reg .u64 t; cvta.to.shared.u64 t, %1; cvt.u32.u64 %0, t; }"
        : "=r"(a) : "l"(p));
    return a;
}

__device__ __forceinline__ void cpasync16(uint32_t dst, const void* src) {
    asm volatile("cp.async.ca.shared.global [%0], [%1], 16;"
                 :: "r"(dst), "l"(src) : "memory");
}

__device__ __forceinline__ void mma_fp16(float* c, const uint32_t* a,
                                         uint32_t b0, uint32_t b1) {
    asm volatile(
        "mma.sync.aligned.m16n8k16.row.col.f32.f16.f16.f32 "
        "{%0,%1,%2,%3}, {%4,%5,%6,%7}, {%8,%9}, {%0,%1,%2,%3};"
        : "+f"(c[0]), "+f"(c[1]), "+f"(c[2]), "+f"(c[3])
        : "r"(a[0]), "r"(a[1]), "r"(a[2]), "r"(a[3]), "r"(b0), "r"(b1));
}

// ---------------------------------------------------------------------------
// CSR build
// ---------------------------------------------------------------------------
__global__ void hist_kernel(const int* __restrict__ rows, int nnz) {
    int e = blockIdx.x * 256 + threadIdx.x;
    if (e < nnz) atomicAdd(&g_row_cnt[__ldg(rows + e)], 1);
}

// Block-local exclusive scan (40 blocks x 1024) + last-block global scan of
// the 40 block totals (replaces the separate scanB kernel).
__global__ __launch_bounds__(256) void scanA_kernel() {
    __shared__ int swarp[8];
    __shared__ int slast;
    const int b = blockIdx.x, tid = threadIdx.x;
    const int lane = tid & 31, wid = tid >> 5;
    int4 v = ((const int4*)g_row_cnt)[b * 256 + tid];
    int tsum = v.x + v.y + v.z + v.w;
    int inc = tsum;
#pragma unroll
    for (int o = 1; o < 32; o <<= 1) {
        int n = __shfl_up_sync(0xffffffffu, inc, o);
        if (lane >= o) inc += n;
    }
    if (lane == 31) swarp[wid] = inc;
    __syncthreads();
    if (wid == 0 && lane < 8) {
        int s = swarp[lane];
        int si = s;
#pragma unroll
        for (int o = 1; o < 8; o <<= 1) {
            int n = __shfl_up_sync(0xffu, si, o);
            if (lane >= o) si += n;
        }
        swarp[lane] = si - s;
        if (lane == 7) {
            g_blk[b] = si;                 // block total
            __threadfence();               // order the store before the ticket
            slast = (atomicAdd(&g_ticket, 1) == 39);
        }
    }
    __syncthreads();
    int base = swarp[wid] + inc - tsum;
    int4 o4;
    o4.x = base;
    o4.y = base + v.x;
    o4.z = o4.y + v.y;
    o4.w = o4.z + v.z;
    ((int4*)g_loc)[b * 256 + tid] = o4;

    // last-arriving block performs the 40-element exclusive scan
    if (slast && tid < 32) {
        __threadfence();
        int l = tid;
        int s0 = (2 * l < 40) ? g_blk[2 * l] : 0;
        int s1 = (2 * l + 1 < 40) ? g_blk[2 * l + 1] : 0;
        int p = s0 + s1, inc2 = p;
#pragma unroll
        for (int o = 1; o < 32; o <<= 1) {
            int n = __shfl_up_sync(0xffffffffu, inc2, o);
            if (l >= o) inc2 += n;
        }
        int excl = inc2 - p;
        if (2 * l < 40) g_blk_off[2 * l] = excl;
        if (2 * l + 1 < 40) g_blk_off[2 * l + 1] = excl + s0;
        if (l == 0) g_ticket = 0;          // reset for next graph replay
    }
}

__global__ void bucket_kernel(const int* __restrict__ rows,
                              const int* __restrict__ cols,
                              const float* __restrict__ vals, int nnz) {
    int e = blockIdx.x * 256 + threadIdx.x;
    if (e >= nnz) return;
    int r = __ldg(rows + e);
    int lp = atomicAdd(&g_loc[r], 1);
    int pos = lp + g_blk_off[r >> 10];
    g_csr_pack[pos] = make_int2(__ldg(cols + e),
                                __float_as_int(__ldg(vals + e)));
}

// ---------------------------------------------------------------------------
// Gather SpMM: warp per row, 4-edge unroll (8 LDG.128 in flight / warp),
// fp32 accumulation, fp16 output.
// ---------------------------------------------------------------------------
__global__ __launch_bounds__(256) void spmm_gather_kernel(
        const float* __restrict__ x) {
    const int wid = threadIdx.x >> 5;
    const int lane = threadIdx.x & 31;
    const int r = blockIdx.x * 8 + wid;

    const int cnt = g_row_cnt[r];
    const int start = g_loc[r] + g_blk_off[r >> 10] - cnt;
    const int2* ep = g_csr_pack + start;

    float a[8];
#pragma unroll
    for (int q = 0; q < 8; ++q) a[q] = 0.f;

    int j = 0;
    for (; j + 4 <= cnt; j += 4) {
        int2 e0 = __ldg(ep + j);
        int2 e1 = __ldg(ep + j + 1);
        int2 e2 = __ldg(ep + j + 2);
        int2 e3 = __ldg(ep + j + 3);
        float v0 = __int_as_float(e0.y);
        float v1 = __int_as_float(e1.y);
        float v2 = __int_as_float(e2.y);
        float v3 = __int_as_float(e3.y);
        const float4* xp0 = (const float4*)(x + (size_t)e0.x * D) + 2 * lane;
        const float4* xp1 = (const float4*)(x + (size_t)e1.x * D) + 2 * lane;
        const float4* xp2 = (const float4*)(x + (size_t)e2.x * D) + 2 * lane;
        const float4* xp3 = (const float4*)(x + (size_t)e3.x * D) + 2 * lane;
        float4 A0 = __ldg(xp0), A1 = __ldg(xp0 + 1);
        float4 B0 = __ldg(xp1), B1 = __ldg(xp1 + 1);
        float4 C0 = __ldg(xp2), C1 = __ldg(xp2 + 1);
        float4 E0 = __ldg(xp3), E1 = __ldg(xp3 + 1);
        a[0] += v0 * A0.x; a[1] += v0 * A0.y; a[2] += v0 * A0.z; a[3] += v0 * A0.w;
        a[4] += v0 * A1.x; a[5] += v0 * A1.y; a[6] += v0 * A1.z; a[7] += v0 * A1.w;
        a[0] += v1 * B0.x; a[1] += v1 * B0.y; a[2] += v1 * B0.z; a[3] += v1 * B0.w;
        a[4] += v1 * B1.x; a[5] += v1 * B1.y; a[6] += v1 * B1.z; a[7] += v1 * B1.w;
        a[0] += v2 * C0.x; a[1] += v2 * C0.y; a[2] += v2 * C0.z; a[3] += v2 * C0.w;
        a[4] += v2 * C1.x; a[5] += v2 * C1.y; a[6] += v2 * C1.z; a[7] += v2 * C1.w;
        a[0] += v3 * E0.x; a[1] += v3 * E0.y; a[2] += v3 * E0.z; a[3] += v3 * E0.w;
        a[4] += v3 * E1.x; a[5] += v3 * E1.y; a[6] += v3 * E1.z; a[7] += v3 * E1.w;
    }
    if (j + 2 <= cnt) {
        int2 e0 = __ldg(ep + j);
        int2 e1 = __ldg(ep + j + 1);
        float v0 = __int_as_float(e0.y);
        float v1 = __int_as_float(e1.y);
        const float4* xp0 = (const float4*)(x + (size_t)e0.x * D) + 2 * lane;
        const float4* xp1 = (const float4*)(x + (size_t)e1.x * D) + 2 * lane;
        float4 A0 = __ldg(xp0), A1 = __ldg(xp0 + 1);
        float4 B0 = __ldg(xp1), B1 = __ldg(xp1 + 1);
        a[0] += v0 * A0.x; a[1] += v0 * A0.y; a[2] += v0 * A0.z; a[3] += v0 * A0.w;
        a[4] += v0 * A1.x; a[5] += v0 * A1.y; a[6] += v0 * A1.z; a[7] += v0 * A1.w;
        a[0] += v1 * B0.x; a[1] += v1 * B0.y; a[2] += v1 * B0.z; a[3] += v1 * B0.w;
        a[4] += v1 * B1.x; a[5] += v1 * B1.y; a[6] += v1 * B1.z; a[7] += v1 * B1.w;
        j += 2;
    }
    if (j < cnt) {
        int2 e0 = __ldg(ep + j);
        float v0 = __int_as_float(e0.y);
        const float4* xp0 = (const float4*)(x + (size_t)e0.x * D) + 2 * lane;
        float4 A0 = __ldg(xp0), A1 = __ldg(xp0 + 1);
        a[0] += v0 * A0.x; a[1] += v0 * A0.y; a[2] += v0 * A0.z; a[3] += v0 * A0.w;
        a[4] += v0 * A1.x; a[5] += v0 * A1.y; a[6] += v0 * A1.z; a[7] += v0 * A1.w;
    }

    __half2 h0 = __floats2half2_rn(a[0], a[1]);
    __half2 h1 = __floats2half2_rn(a[2], a[3]);
    __half2 h2 = __floats2half2_rn(a[4], a[5]);
    __half2 h3 = __floats2half2_rn(a[6], a[7]);
    uint4 pack = make_uint4(*(uint32_t*)&h0, *(uint32_t*)&h1,
                            *(uint32_t*)&h2, *(uint32_t*)&h3);
    *(uint4*)(g_mapped_h + (size_t)r * D + lane * 8) = pack;
}

// ---------------------------------------------------------------------------
// W transpose -> fp16: 32x32 tiles.
// ---------------------------------------------------------------------------
__global__ __launch_bounds__(256) void wconv_kernel(const float* __restrict__ W) {
    __shared__ float t[32][33];
    const int tid = threadIdx.x;
    const int k0 = (blockIdx.x >> 3) * 32;
    const int n0 = (blockIdx.x & 7) * 32;
    {
        int row = tid >> 3, c4 = tid & 7;
        float4 v = __ldg((const float4*)(W + (size_t)(k0 + row) * D + n0 + c4 * 4));
        t[row][c4 * 4 + 0] = v.x;
        t[row][c4 * 4 + 1] = v.y;
        t[row][c4 * 4 + 2] = v.z;
        t[row][c4 * 4 + 3] = v.w;
    }
    __syncthreads();
    {
        int nl = tid >> 3, kq = (tid & 7) * 4;
        __half2 p0 = __floats2half2_rn(t[kq][nl], t[kq + 1][nl]);
        __half2 p1 = __floats2half2_rn(t[kq + 2][nl], t[kq + 3][nl]);
        uint2 pk = make_uint2(*(uint32_t*)&p0, *(uint32_t*)&p1);
        *(uint2*)(g_wt_h + (size_t)(n0 + nl) * D + k0 + kq) = pk;
    }
}

// ---------------------------------------------------------------------------
// Persistent GEMM (proven R12): 148 CTAs, B resident, double-buffered A,
// mapped@W + bias + LN + GELU.
// ---------------------------------------------------------------------------
extern __shared__ char dynsmem[];

__global__ __launch_bounds__(256, 1) void gemm_ln_gelu_kernel(
        const float* __restrict__ bias,
        const float* __restrict__ gamma,
        const float* __restrict__ beta,
        float* __restrict__ out) {
    char* sm = dynsmem;
    const uint32_t sb = smem_u32(sm);
    const int tid = threadIdx.x;
    const int wid = tid >> 5;
    const int lane = tid & 31;
    const int gr = lane >> 2;
    const int tc = lane & 3;
    const int warp_m = wid & 1;
    const int warp_n = wid >> 1;

    ((float*)(sm + OFF_BIAS))[tid]  = bias[tid];
    ((float*)(sm + OFF_GAMMA))[tid] = gamma[tid];
    ((float*)(sm + OFF_BETA))[tid]  = beta[tid];

#pragma unroll
    for (int i = 0; i < 32; ++i) {
        int task = i * 256 + tid;
        int n = task >> 5, seg = task & 31;
        cpasync16(sb + OFF_B + n * 528 + seg * 16, g_wt_h + n * 256 + seg * 8);
    }
    asm volatile("cp.async.commit_group;" ::: "memory");

    {
        int t0 = blockIdx.x;
#pragma unroll
        for (int i = 0; i < 8; ++i) {
            int task = i * 256 + tid;
            int row = task >> 5, seg = task & 31;
            cpasync16(sb + OFF_A0 + row * 528 + seg * 16,
                      g_mapped_h + (size_t)(t0 * BM + row) * D + seg * 8);
        }
        asm volatile("cp.async.commit_group;" ::: "memory");
    }

    const float* sBias = (const float*)(sm + OFF_BIAS);
    const float* sG    = (const float*)(sm + OFF_GAMMA);
    const float* sBe   = (const float*)(sm + OFF_BETA);
    float2* sPart = (float2*)(sm + OFF_PART);
    float2* sStat = (float2*)(sm + OFF_STAT);

    int i = 0;
#pragma unroll 1
    for (int t = blockIdx.x; t < NTILE; t += GRID, ++i) {
        asm volatile("cp.async.wait_group 0;" ::: "memory");
        __syncthreads();

        if (t + GRID < NTILE) {
            uint32_t nb = sb + ((i + 1) & 1 ? OFF_A1 : OFF_A0);
#pragma unroll
            for (int p = 0; p < 8; ++p) {
                int task = p * 256 + tid;
                int row = task >> 5, seg = task & 31;
                cpasync16(nb + row * 528 + seg * 16,
                          g_mapped_h + (size_t)((t + GRID) * BM + row) * D + seg * 8);
            }
            asm volatile("cp.async.commit_group;" ::: "memory");
        }

        const uint16_t* pA = (const uint16_t*)(sm + ((i & 1) ? OFF_A1 : OFF_A0));
        const uint16_t* pB = (const uint16_t*)(sm + OFF_B);

        float acc[2][8][4];
#pragma unroll
        for (int mt = 0; mt < 2; ++mt)
#pragma unroll
            for (int nt = 0; nt < 8; ++nt)
#pragma unroll
                for (int q = 0; q < 4; ++q) acc[mt][nt][q] = 0.f;

#pragma unroll
        for (int ks = 0; ks < 16; ++ks) {
            uint32_t a[2][4];
#pragma unroll
            for (int mt = 0; mt < 2; ++mt) {
                const uint16_t* ph = pA + (warp_m * 32 + mt * 16 + gr) * A_STRIDE
                                        + ks * 16 + tc * 2;
                a[mt][0] = *(const uint32_t*)(ph);
                a[mt][1] = *(const uint32_t*)(ph + 8 * A_STRIDE);
                a[mt][2] = *(const uint32_t*)(ph + 8);
                a[mt][3] = *(const uint32_t*)(ph + 8 * A_STRIDE + 8);
            }
#pragma unroll
            for (int nt = 0; nt < 8; ++nt) {
                const uint16_t* pb = pB + (warp_n * 64 + nt * 8 + gr) * A_STRIDE
                                        + ks * 16 + tc * 2;
                uint32_t b0 = *(const uint32_t*)(pb);
                uint32_t b1 = *(const uint32_t*)(pb + 8);
                mma_fp16(acc[0][nt], a[0], b0, b1);
                mma_fp16(acc[1][nt], a[1], b0, b1);
            }
        }

        float s[2][2], q[2][2];
#pragma unroll
        for (int mt = 0; mt < 2; ++mt)
#pragma unroll
            for (int h = 0; h < 2; ++h) { s[mt][h] = 0.f; q[mt][h] = 0.f; }

#pragma unroll
        for (int mt = 0; mt < 2; ++mt)
#pragma unroll
            for (int nt = 0; nt < 8; ++nt) {
                int c = warp_n * 64 + nt * 8 + tc * 2;
                float b0 = sBias[c], b1 = sBias[c + 1];
#pragma unroll
                for (int h = 0; h < 2; ++h) {
                    float v0 = acc[mt][nt][2 * h] + b0;
                    float v1 = acc[mt][nt][2 * h + 1] + b1;
                    acc[mt][nt][2 * h] = v0;
                    acc[mt][nt][2 * h + 1] = v1;
                    s[mt][h] += v0 + v1;
                    q[mt][h] += v0 * v0 + v1 * v1;
                }
            }
#pragma unroll
        for (int mt = 0; mt < 2; ++mt)
#pragma unroll
            for (int h = 0; h < 2; ++h) {
#pragma unroll
                for (int o = 1; o < 4; o <<= 1) {
                    s[mt][h] += __shfl_xor_sync(0xffffffffu, s[mt][h], o);
                    q[mt][h] += __shfl_xor_sync(0xffffffffu, q[mt][h], o);
                }
            }
        if (tc == 0) {
#pragma unroll
            for (int mt = 0; mt < 2; ++mt)
#pragma unroll
                for (int h = 0; h < 2; ++h) {
                    int r = warp_m * 32 + mt * 16 + 8 * h + gr;
                    sPart[r * 4 + warp_n] = make_float2(s[mt][h], q[mt][h]);
                }
        }
        __syncthreads();
        if (tid < 64) {
            float2 p0 = sPart[tid * 4 + 0];
            float2 p1 = sPart[tid * 4 + 1];
            float2 p2 = sPart[tid * 4 + 2];
            float2 p3 = sPart[tid * 4 + 3];
            float S = p0.x + p1.x + p2.x + p3.x;
            float Q = p0.y + p1.y + p2.y + p3.y;
            float mu = S * (1.f / 256.f);
            float var = Q * (1.f / 256.f) - mu * mu;
            sStat[tid] = make_float2(mu, rsqrtf(fmaxf(var, 0.f) + 1e-5f));
        }
        __syncthreads();

#pragma unroll
        for (int mt = 0; mt < 2; ++mt)
#pragma unroll
            for (int h = 0; h < 2; ++h) {
                int r = warp_m * 32 + mt * 16 + 8 * h + gr;
                float2 st = sStat[r];
                float* orow = out + (size_t)(t * BM + r) * D;
#pragma unroll
                for (int nt = 0; nt < 8; ++nt) {
                    int c = warp_n * 64 + nt * 8 + tc * 2;
                    float t0 = (acc[mt][nt][2 * h] - st.x) * st.y * sG[c] + sBe[c];
                    float t1 = (acc[mt][nt][2 * h + 1] - st.x) * st.y * sG[c + 1] + sBe[c + 1];
                    float2 g;
                    g.x = 0.5f * t0 * (1.f + erff(t0 * 0.70710678118654752f));
                    g.y = 0.5f * t1 * (1.f + erff(t1 * 0.70710678118654752f));
                    *(float2*)(orow + c) = g;
                }
            }
    }
}

// ---------------------------------------------------------------------------
// Launch
// ---------------------------------------------------------------------------
extern "C" void kernel_launch(void* const* d_in, const int* in_sizes, int n_in,
                              void* d_out, int out_size) {
    const float* x     = (const float*)d_in[0];
    const int*   rows  = (const int*)d_in[1];
    const int*   cols  = (const int*)d_in[2];
    const float* vals  = (const float*)d_in[3];
    const float* W     = (const float*)d_in[4];
    const float* bias  = (const float*)d_in[5];
    const float* gamma = (const float*)d_in[6];
    const float* beta  = (const float*)d_in[7];

    const int nnz = in_sizes[1];
    const int eblk = (nnz + 255) / 256;

    void* cnt_ptr = nullptr;
    cudaGetSymbolAddress(&cnt_ptr, g_row_cnt);
    cudaMemsetAsync(cnt_ptr, 0, N_TGT_PAD * sizeof(int));

    hist_kernel<<<eblk, 256>>>(rows, nnz);
    scanA_kernel<<<40, 256>>>();            // includes the 40-block scan (ex-scanB)
    bucket_kernel<<<eblk, 256>>>(rows, cols, vals, nnz);

    spmm_gather_kernel<<<N_TGT / 8, 256>>>(x);
    wconv_kernel<<<64, 256>>>(W);

    cudaFuncSetAttribute(gemm_ln_gelu_kernel,
                         cudaFuncAttributeMaxDynamicSharedMemorySize,
                         SMEM_TOTAL);
    gemm_ln_gelu_kernel<<<GRID, 256, SMEM_TOTAL>>>(
        bias, gamma, beta, (float*)d_out);
}